// round 1
// baseline (speedup 1.0000x reference)
#include <cuda_runtime.h>

#define NTOK 16384
#define DM   1024
#define NH   16
#define HD   64

// Scratch (device globals: allocation-free per harness rules)
__device__ float g_qh[(size_t)NTOK * DM];
__device__ float g_kh[(size_t)NTOK * DM];
__device__ float g_vh[(size_t)NTOK * DM];
__device__ float g_att[(size_t)NTOK * DM];

__device__ __forceinline__ unsigned f2tf32(float f) {
    unsigned u;
    asm("cvt.rna.tf32.f32 %0, %1;" : "=r"(u) : "f"(f));
    return u;
}

// ---------------------------------------------------------------------------
// GEMM: C[M,Nc] = A[M,K] * W[Nc,K]^T + bias[Nc]   (torch Linear semantics)
// TF32 mma.sync, BM=128 BN=128 BK=16, 256 threads (8 warps, 4x2),
// warp tile 32x64 (2 m16 x 8 n8 fragments).
// ---------------------------------------------------------------------------
#define BM 128
#define BN 128
#define BK 16
#define LDSS 20   // padded smem row stride (words): conflict-free frag loads

__global__ __launch_bounds__(256)
void gemm_tf32_bias(const float* __restrict__ A,
                    const float* __restrict__ W,
                    const float* __restrict__ bias,
                    float* __restrict__ C,
                    int M, int Nc, int K)
{
    __shared__ unsigned As[BM * LDSS];
    __shared__ unsigned Bs[BN * LDSS];

    const int t    = threadIdx.x;
    const int warp = t >> 5;
    const int lane = t & 31;
    const int wm   = warp >> 1;     // 0..3  (m)
    const int wn   = warp & 1;      // 0..1  (n)
    const int gq   = lane >> 2;     // groupID 0..7
    const int tg   = lane & 3;      // threadID_in_group 0..3

    const int m0 = blockIdx.y * BM;
    const int n0 = blockIdx.x * BN;

    float acc[2][8][4];
    #pragma unroll
    for (int mi = 0; mi < 2; mi++)
        #pragma unroll
        for (int ni = 0; ni < 8; ni++)
            #pragma unroll
            for (int r = 0; r < 4; r++) acc[mi][ni][r] = 0.f;

    const int lr = t >> 2;   // 0..63 : tile row for staging
    const int lc = t & 3;    // float4 column index

    for (int kt = 0; kt < K; kt += BK) {
        // Stage A (X rows) and B (W rows) tiles, rounding to tf32 (rna).
        #pragma unroll
        for (int half = 0; half < 2; half++) {
            int row = lr + half * 64;
            float4 va = *(const float4*)(A + (size_t)(m0 + row) * K + kt + lc * 4);
            unsigned* da = &As[row * LDSS + lc * 4];
            da[0] = f2tf32(va.x); da[1] = f2tf32(va.y);
            da[2] = f2tf32(va.z); da[3] = f2tf32(va.w);
            float4 vb = *(const float4*)(W + (size_t)(n0 + row) * K + kt + lc * 4);
            unsigned* db = &Bs[row * LDSS + lc * 4];
            db[0] = f2tf32(vb.x); db[1] = f2tf32(vb.y);
            db[2] = f2tf32(vb.z); db[3] = f2tf32(vb.w);
        }
        __syncthreads();

        #pragma unroll
        for (int kk = 0; kk < 2; kk++) {
            unsigned a[2][4];
            #pragma unroll
            for (int mi = 0; mi < 2; mi++) {
                int ar = wm * 32 + mi * 16 + gq;
                int ac = kk * 8 + tg;
                a[mi][0] = As[ar * LDSS + ac];
                a[mi][1] = As[(ar + 8) * LDSS + ac];
                a[mi][2] = As[ar * LDSS + ac + 4];
                a[mi][3] = As[(ar + 8) * LDSS + ac + 4];
            }
            unsigned b[8][2];
            #pragma unroll
            for (int ni = 0; ni < 8; ni++) {
                int br = wn * 64 + ni * 8 + gq;
                int bc = kk * 8 + tg;
                b[ni][0] = Bs[br * LDSS + bc];
                b[ni][1] = Bs[br * LDSS + bc + 4];
            }
            #pragma unroll
            for (int mi = 0; mi < 2; mi++)
                #pragma unroll
                for (int ni = 0; ni < 8; ni++) {
                    asm volatile(
                        "mma.sync.aligned.m16n8k8.row.col.f32.tf32.tf32.f32 "
                        "{%0,%1,%2,%3}, {%4,%5,%6,%7}, {%8,%9}, {%0,%1,%2,%3};\n"
                        : "+f"(acc[mi][ni][0]), "+f"(acc[mi][ni][1]),
                          "+f"(acc[mi][ni][2]), "+f"(acc[mi][ni][3])
                        : "r"(a[mi][0]), "r"(a[mi][1]), "r"(a[mi][2]), "r"(a[mi][3]),
                          "r"(b[ni][0]), "r"(b[ni][1]));
                }
        }
        __syncthreads();
    }

    // Epilogue: bias add + fp32 store
    #pragma unroll
    for (int mi = 0; mi < 2; mi++) {
        int row = m0 + wm * 32 + mi * 16 + gq;
        #pragma unroll
        for (int ni = 0; ni < 8; ni++) {
            int col = n0 + wn * 64 + ni * 8 + tg * 2;
            float b0 = bias[col], b1 = bias[col + 1];
            float2 v0 = make_float2(acc[mi][ni][0] + b0, acc[mi][ni][1] + b1);
            float2 v1 = make_float2(acc[mi][ni][2] + b0, acc[mi][ni][3] + b1);
            *(float2*)(C + (size_t)row * Nc + col)       = v0;
            *(float2*)(C + (size_t)(row + 8) * Nc + col) = v1;
        }
    }
}

// ---------------------------------------------------------------------------
// Per-token head-mixing attention (exact fp32).
// One block (256 threads) per token: scores[16][16] = qh kh^T / 8,
// softmax over g, out = attn @ vh.
// ---------------------------------------------------------------------------
__global__ __launch_bounds__(256)
void head_attn(const float* __restrict__ qh, const float* __restrict__ kh,
               const float* __restrict__ vh, float* __restrict__ out)
{
    __shared__ float qs[NH][HD + 4];
    __shared__ float ks[NH][HD + 4];
    __shared__ float vs[NH][HD + 4];
    __shared__ float sc[NH][NH + 1];

    const int tok = blockIdx.x;
    const int t   = threadIdx.x;
    const size_t base = (size_t)tok * DM;

    {
        int row = t >> 4;             // 0..15 (head)
        int c4  = (t & 15) * 4;       // 0..60
        *(float4*)&qs[row][c4] = *(const float4*)(qh + base + row * HD + c4);
        *(float4*)&ks[row][c4] = *(const float4*)(kh + base + row * HD + c4);
        *(float4*)&vs[row][c4] = *(const float4*)(vh + base + row * HD + c4);
    }
    __syncthreads();

    {
        int h = t >> 4, g = t & 15;   // one score per thread
        float s = 0.f;
        #pragma unroll
        for (int d = 0; d < HD; d++) s += qs[h][d] * ks[g][d];
        sc[h][g] = s * 0.125f;        // / sqrt(64)
    }
    __syncthreads();

    if (t < NH) {                     // softmax, one row per thread
        float m = sc[t][0];
        #pragma unroll
        for (int g = 1; g < NH; g++) m = fmaxf(m, sc[t][g]);
        float e[NH], sum = 0.f;
        #pragma unroll
        for (int g = 0; g < NH; g++) { e[g] = __expf(sc[t][g] - m); sum += e[g]; }
        float inv = 1.f / sum;
        #pragma unroll
        for (int g = 0; g < NH; g++) sc[t][g] = e[g] * inv;
    }
    __syncthreads();

    #pragma unroll
    for (int i = 0; i < 4; i++) {
        int e = i * 256 + t;          // coalesced over 1024 outputs
        int h = e >> 6, d = e & 63;
        float a = 0.f;
        #pragma unroll
        for (int g = 0; g < NH; g++) a += sc[h][g] * vs[g][d];
        out[base + e] = a;
    }
}

// ---------------------------------------------------------------------------
// kernel_launch: 3 projection GEMMs -> attention -> output GEMM
// ---------------------------------------------------------------------------
extern "C" void kernel_launch(void* const* d_in, const int* in_sizes, int n_in,
                              void* d_out, int out_size)
{
    const float* q  = (const float*)d_in[0];
    const float* k  = (const float*)d_in[1];
    const float* v  = (const float*)d_in[2];
    const float* Wq = (const float*)d_in[3];
    const float* bq = (const float*)d_in[4];
    const float* Wk = (const float*)d_in[5];
    const float* bk = (const float*)d_in[6];
    const float* Wv = (const float*)d_in[7];
    const float* bv = (const float*)d_in[8];
    const float* Wo = (const float*)d_in[9];
    const float* bo = (const float*)d_in[10];
    float* out = (float*)d_out;

    float *qh, *kh, *vh, *att;
    cudaGetSymbolAddress((void**)&qh,  g_qh);
    cudaGetSymbolAddress((void**)&kh,  g_kh);
    cudaGetSymbolAddress((void**)&vh,  g_vh);
    cudaGetSymbolAddress((void**)&att, g_att);

    dim3 gg(DM / BN, NTOK / BM);
    gemm_tf32_bias<<<gg, 256>>>(q, Wq, bq, qh, NTOK, DM, DM);
    gemm_tf32_bias<<<gg, 256>>>(k, Wk, bk, kh, NTOK, DM, DM);
    gemm_tf32_bias<<<gg, 256>>>(v, Wv, bv, vh, NTOK, DM, DM);
    head_attn<<<NTOK, 256>>>(qh, kh, vh, att);
    gemm_tf32_bias<<<gg, 256>>>(att, Wo, bo, out, NTOK, DM, DM);
}

// round 4
// speedup vs baseline: 1.0532x; 1.0532x over previous
#include <cuda_runtime.h>
#include <cstdint>

#define NTOK 16384
#define DM   1024
#define NH   16
#define HD   64
#define KD   1024

// ---------------- scratch ----------------
__device__ float g_qh [(size_t)NTOK * DM];
__device__ float g_kh [(size_t)NTOK * DM];
__device__ float g_vh [(size_t)NTOK * DM];
__device__ float g_att[(size_t)NTOK * DM];

__device__ __forceinline__ float f2tf32f(float f) {
    unsigned u;
    asm("cvt.rna.tf32.f32 %0, %1;" : "=r"(u) : "f"(f));
    return __uint_as_float(u);
}

// ---------------------------------------------------------------------------
// GEMM: C[M,1024] = A[M,1024] @ W[1024,1024]^T + bias   (tf32 mma.sync)
// BM=128 BN=256 BK=32, 256 thr, 8 warps (2x4), warp tile 64x64.
// Smem layout: per stage, per k-group (8 k), rows of 8 floats storing
// permuted pairs (k, k+4) at pair slot jp = p ^ (row&3)  -> all fragment
// reads are conflict-free LDS.64; plane stride 1032 words (= 8 mod 32)
// makes the STS pattern conflict-free too.
// ---------------------------------------------------------------------------
#define BM 128
#define BN 256
#define BK 32
#define NKT (KD / BK)        // 32
#define PA 1032              // words per A k-group plane (128*8 + 8)
#define PB 2056              // words per B k-group plane (256*8 + 8)
#define ASTG (4 * PA)        // 4128 words per A stage
#define BSTG (4 * PB)        // 8224 words per B stage
#define BOFF (2 * ASTG)      // B region starts after both A stages
#define GEMM_SMEM_BYTES ((2 * ASTG + 2 * BSTG) * 4)   // 98816

#define MMA_TF32(acc, ax, bx)                                                   \
    asm volatile("mma.sync.aligned.m16n8k8.row.col.f32.tf32.tf32.f32 "          \
                 "{%0,%1,%2,%3}, {%4,%5,%6,%7}, {%8,%9}, {%0,%1,%2,%3};\n"      \
                 : "+f"((acc)[0]), "+f"((acc)[1]), "+f"((acc)[2]), "+f"((acc)[3]) \
                 : "r"(__float_as_uint((ax)[0])), "r"(__float_as_uint((ax)[1])), \
                   "r"(__float_as_uint((ax)[2])), "r"(__float_as_uint((ax)[3])), \
                   "r"(__float_as_uint((bx).x)),  "r"(__float_as_uint((bx).y)))

__global__ __launch_bounds__(256, 1)
void gemm_tc(const float* __restrict__ A, const float* __restrict__ W,
             const float* __restrict__ bias, float* __restrict__ C)
{
    extern __shared__ float sm[];

    const int t    = threadIdx.x;
    const int warp = t >> 5;
    const int lane = t & 31;
    const int wm   = warp >> 2;       // 0..1
    const int wn   = warp & 3;        // 0..3
    const int gq   = lane >> 2;       // 0..7
    const int tg   = lane & 3;        // 0..3

    const int m0 = blockIdx.y * BM;
    const int n0 = blockIdx.x * BN;   // x = n so concurrent blocks share A in L2

    const int srow = t >> 2;          // 0..63
    const int skg  = t & 3;           // 0..3
    const int rx   = srow & 3;        // swizzle key for staging rows

    const float* Ag = A + (size_t)(m0 + srow) * KD + skg * 8;
    const float* Wg = W + (size_t)(n0 + srow) * KD + skg * 8;

    float4 ra[2][2];                  // A: 2 chunks (rows srow, srow+64)
    float4 rb[4][2];                  // B: 4 chunks (rows srow + c*64)

    auto LDG = [&](int kt) {
        #pragma unroll
        for (int c = 0; c < 2; c++) {
            const float* p = Ag + (size_t)(c * 64) * KD + kt * BK;
            ra[c][0] = __ldg((const float4*)p);
            ra[c][1] = __ldg((const float4*)(p + 4));
        }
        #pragma unroll
        for (int c = 0; c < 4; c++) {
            const float* p = Wg + (size_t)(c * 64) * KD + kt * BK;
            rb[c][0] = __ldg((const float4*)p);
            rb[c][1] = __ldg((const float4*)(p + 4));
        }
    };

    auto STS = [&](int s) {
        #pragma unroll
        for (int c = 0; c < 2; c++) {
            int r = srow + c * 64;
            float* base = sm + s * ASTG + skg * PA + r * 8;
            float v[8] = { ra[c][0].x, ra[c][0].y, ra[c][0].z, ra[c][0].w,
                           ra[c][1].x, ra[c][1].y, ra[c][1].z, ra[c][1].w };
            #pragma unroll
            for (int p = 0; p < 4; p++) {
                int jp = (p ^ rx) * 2;
                *(float2*)(base + jp) = make_float2(f2tf32f(v[p]), f2tf32f(v[p + 4]));
            }
        }
        #pragma unroll
        for (int c = 0; c < 4; c++) {
            int r = srow + c * 64;
            float* base = sm + BOFF + s * BSTG + skg * PB + r * 8;
            float v[8] = { rb[c][0].x, rb[c][0].y, rb[c][0].z, rb[c][0].w,
                           rb[c][1].x, rb[c][1].y, rb[c][1].z, rb[c][1].w };
            #pragma unroll
            for (int p = 0; p < 4; p++) {
                int jp = (p ^ rx) * 2;
                *(float2*)(base + jp) = make_float2(f2tf32f(v[p]), f2tf32f(v[p + 4]));
            }
        }
    };

    float acc[4][8][4];
    #pragma unroll
    for (int mi = 0; mi < 4; mi++)
        #pragma unroll
        for (int ni = 0; ni < 8; ni++)
            #pragma unroll
            for (int r = 0; r < 4; r++) acc[mi][ni][r] = 0.f;

    const int jp = (tg ^ (gq & 3)) * 2;   // pair word offset for fragment loads

    auto COMPUTE = [&](int s) {
        #pragma unroll
        for (int kg = 0; kg < 4; kg++) {
            const float* Abase = sm + s * ASTG + kg * PA;
            const float* Bbase = sm + BOFF + s * BSTG + kg * PB;
            float a[4][4];
            #pragma unroll
            for (int mi = 0; mi < 4; mi++) {
                int r1 = wm * 64 + mi * 16 + gq;
                float2 lo = *(const float2*)(Abase + r1 * 8 + jp);
                float2 hi = *(const float2*)(Abase + (r1 + 8) * 8 + jp);
                a[mi][0] = lo.x; a[mi][1] = hi.x;   // rows gq, gq+8 @ col tg
                a[mi][2] = lo.y; a[mi][3] = hi.y;   // rows gq, gq+8 @ col tg+4
            }
            #pragma unroll
            for (int ni = 0; ni < 8; ni++) {
                int rn = wn * 64 + ni * 8 + gq;
                float2 bb = *(const float2*)(Bbase + rn * 8 + jp);
                #pragma unroll
                for (int mi = 0; mi < 4; mi++)
                    MMA_TF32(acc[mi][ni], a[mi], bb);
            }
        }
    };

    // --------------- pipeline: 2-stage smem + 1-tile register prefetch --------
    LDG(0);
    STS(0);
    LDG(1);
    __syncthreads();

    for (int kt = 0; kt < NKT; kt++) {
        const int buf = kt & 1;
        if (kt + 1 < NKT) STS(buf ^ 1);     // stage data for kt+1
        if (kt + 2 < NKT) LDG(kt + 2);      // prefetch kt+2 into regs
        COMPUTE(buf);
        __syncthreads();
    }

    // --------------- epilogue: bias + STG.64 ---------------------------------
    #pragma unroll
    for (int mi = 0; mi < 4; mi++) {
        int r = m0 + wm * 64 + mi * 16 + gq;
        #pragma unroll
        for (int ni = 0; ni < 8; ni++) {
            int cc = n0 + wn * 64 + ni * 8 + tg * 2;
            float b0 = __ldg(bias + cc);
            float b1 = __ldg(bias + cc + 1);
            *(float2*)(C + (size_t)r * DM + cc) =
                make_float2(acc[mi][ni][0] + b0, acc[mi][ni][1] + b1);
            *(float2*)(C + (size_t)(r + 8) * DM + cc) =
                make_float2(acc[mi][ni][2] + b0, acc[mi][ni][3] + b1);
        }
    }
}

// ---------------------------------------------------------------------------
// Per-token head-mixing attention (exact fp32), float4-vectorized.
// ---------------------------------------------------------------------------
__global__ __launch_bounds__(256)
void head_attn(const float* __restrict__ qh, const float* __restrict__ kh,
               const float* __restrict__ vh, float* __restrict__ out)
{
    __shared__ float qs[NH][HD + 4];
    __shared__ float ks[NH][HD + 4];
    __shared__ float vs[NH][HD + 4];
    __shared__ float sc[NH][NH + 1];

    const int tok = blockIdx.x;
    const int t   = threadIdx.x;
    const size_t base = (size_t)tok * DM;

    {
        int row = t >> 4;
        int c4  = (t & 15) * 4;
        *(float4*)&qs[row][c4] = *(const float4*)(qh + base + row * HD + c4);
        *(float4*)&ks[row][c4] = *(const float4*)(kh + base + row * HD + c4);
        *(float4*)&vs[row][c4] = *(const float4*)(vh + base + row * HD + c4);
    }
    __syncthreads();

    {
        int h = t >> 4, g = t & 15;
        float s = 0.f;
        #pragma unroll
        for (int d4 = 0; d4 < HD; d4 += 4) {
            float4 a = *(const float4*)&qs[h][d4];
            float4 b = *(const float4*)&ks[g][d4];
            s += a.x * b.x + a.y * b.y + a.z * b.z + a.w * b.w;
        }
        sc[h][g] = s * 0.125f;
    }
    __syncthreads();

    if (t < NH) {
        float m = sc[t][0];
        #pragma unroll
        for (int g = 1; g < NH; g++) m = fmaxf(m, sc[t][g]);
        float e[NH], sum = 0.f;
        #pragma unroll
        for (int g = 0; g < NH; g++) { e[g] = __expf(sc[t][g] - m); sum += e[g]; }
        float inv = 1.f / sum;
        #pragma unroll
        for (int g = 0; g < NH; g++) sc[t][g] = e[g] * inv;
    }
    __syncthreads();

    {
        int h  = t >> 4;
        int d4 = (t & 15) * 4;
        float4 acc = make_float4(0.f, 0.f, 0.f, 0.f);
        #pragma unroll
        for (int g = 0; g < NH; g++) {
            float w = sc[h][g];
            float4 vv = *(const float4*)&vs[g][d4];
            acc.x += w * vv.x; acc.y += w * vv.y;
            acc.z += w * vv.z; acc.w += w * vv.w;
        }
        *(float4*)(out + base + h * HD + d4) = acc;
    }
}

// ---------------------------------------------------------------------------
extern "C" void kernel_launch(void* const* d_in, const int* in_sizes, int n_in,
                              void* d_out, int out_size)
{
    const float* q  = (const float*)d_in[0];
    const float* k  = (const float*)d_in[1];
    const float* v  = (const float*)d_in[2];
    const float* Wq = (const float*)d_in[3];
    const float* bq = (const float*)d_in[4];
    const float* Wk = (const float*)d_in[5];
    const float* bk = (const float*)d_in[6];
    const float* Wv = (const float*)d_in[7];
    const float* bv = (const float*)d_in[8];
    const float* Wo = (const float*)d_in[9];
    const float* bo = (const float*)d_in[10];
    float* out = (float*)d_out;

    float *qh, *kh, *vh, *att;
    cudaGetSymbolAddress((void**)&qh,  g_qh);
    cudaGetSymbolAddress((void**)&kh,  g_kh);
    cudaGetSymbolAddress((void**)&vh,  g_vh);
    cudaGetSymbolAddress((void**)&att, g_att);

    cudaFuncSetAttribute(gemm_tc, cudaFuncAttributeMaxDynamicSharedMemorySize,
                         GEMM_SMEM_BYTES);

    dim3 gg(DM / BN, NTOK / BM);   // (4, 128)
    gemm_tc<<<gg, 256, GEMM_SMEM_BYTES>>>(q,   Wq, bq, qh);
    gemm_tc<<<gg, 256, GEMM_SMEM_BYTES>>>(k,   Wk, bk, kh);
    gemm_tc<<<gg, 256, GEMM_SMEM_BYTES>>>(v,   Wv, bv, vh);
    head_attn<<<NTOK, 256>>>(qh, kh, vh, att);
    gemm_tc<<<gg, 256, GEMM_SMEM_BYTES>>>(att, Wo, bo, out);
}

// round 5
// speedup vs baseline: 2.2596x; 2.1454x over previous
#include <cuda_runtime.h>
#include <cuda_fp16.h>
#include <cstdint>

#define NTOK 16384
#define DM   1024
#define NH   16
#define HD   64
#define KD   1024

// ---------------- scratch (fp16 copies + intermediates) ----------------
__device__ __half g_hq [(size_t)NTOK * DM];
__device__ __half g_hk [(size_t)NTOK * DM];
__device__ __half g_hv [(size_t)NTOK * DM];
__device__ __half g_hWq[(size_t)DM * DM];
__device__ __half g_hWk[(size_t)DM * DM];
__device__ __half g_hWv[(size_t)DM * DM];
__device__ __half g_hWo[(size_t)DM * DM];
__device__ __half g_qh [(size_t)NTOK * DM];
__device__ __half g_kh [(size_t)NTOK * DM];
__device__ __half g_vh [(size_t)NTOK * DM];
__device__ __half g_att[(size_t)NTOK * DM];

__device__ __forceinline__ uint32_t smem_u32(const void* p) {
    uint32_t a;
    asm("{ .reg .u64 t; cvta.to.shared.u64 t, %1; cvt.u32.u64 %0, t; }" : "=r"(a) : "l"(p));
    return a;
}

// ---------------------------------------------------------------------------
// GEMM: C[M,1024] = A[M,1024] @ W[1024,1024]^T + bias   (fp16 in, fp32 acc)
// BM=128 BN=256 BK=64, 256 thr, 8 warps (2x4), warp tile 64x64.
// 3-stage cp.async pipeline; XOR-swizzled 128B rows; ldmatrix.x4 frags.
// ---------------------------------------------------------------------------
#define BM 128
#define BN 256
#define BK 64
#define NKT (KD / BK)            // 16
#define ASTG 16384               // bytes per A stage (128 rows x 128B)
#define BSTG 32768               // bytes per B stage (256 rows x 128B)
#define BOFF (3 * ASTG)          // 49152
#define GEMM_SMEM (3 * ASTG + 3 * BSTG)   // 147456

#define LDSM_X4(r0, r1, r2, r3, addr)                                           \
    asm volatile("ldmatrix.sync.aligned.m8n8.x4.shared.b16 {%0,%1,%2,%3}, [%4];" \
                 : "=r"(r0), "=r"(r1), "=r"(r2), "=r"(r3) : "r"(addr))

#define MMA_F16(acc, a, b0, b1)                                                 \
    asm volatile("mma.sync.aligned.m16n8k16.row.col.f32.f16.f16.f32 "           \
                 "{%0,%1,%2,%3}, {%4,%5,%6,%7}, {%8,%9}, {%0,%1,%2,%3};\n"      \
                 : "+f"((acc)[0]), "+f"((acc)[1]), "+f"((acc)[2]), "+f"((acc)[3]) \
                 : "r"((a)[0]), "r"((a)[1]), "r"((a)[2]), "r"((a)[3]),          \
                   "r"(b0), "r"(b1))

#define CP_ASYNC16(dst, src) \
    asm volatile("cp.async.cg.shared.global [%0], [%1], 16;" :: "r"(dst), "l"(src))
#define CP_COMMIT() asm volatile("cp.async.commit_group;")
#define CP_WAIT1()  asm volatile("cp.async.wait_group 1;")

template <typename OutT>
__global__ __launch_bounds__(256, 1)
void gemm_h(const __half* __restrict__ A, const __half* __restrict__ W,
            const float* __restrict__ bias, OutT* __restrict__ C)
{
    extern __shared__ char smem[];
    const uint32_t sb = smem_u32(smem);

    const int t    = threadIdx.x;
    const int warp = t >> 5;
    const int lane = t & 31;
    const int wm   = warp >> 2;          // 0..1
    const int wn   = warp & 3;           // 0..3
    const int m0   = blockIdx.y * BM;
    const int n0   = blockIdx.x * BN;

    // cp.async chunk assignment
    const int arow = t >> 1;             // unused granularity; use id scheme below

    auto stage = [&](int kt) {
        const int s = kt % 3;
        const uint32_t sa = sb + s * ASTG;
        const uint32_t sw = sb + BOFF + s * BSTG;
        #pragma unroll
        for (int i = 0; i < 4; i++) {            // A: 1024 16B chunks
            int id  = t + i * 256;
            int row = id >> 3, c16 = id & 7;
            const __half* src = A + (size_t)(m0 + row) * KD + kt * BK + c16 * 8;
            CP_ASYNC16(sa + row * 128 + ((c16 ^ (row & 7)) << 4), src);
        }
        #pragma unroll
        for (int i = 0; i < 8; i++) {            // B: 2048 16B chunks
            int id  = t + i * 256;
            int row = id >> 3, c16 = id & 7;
            const __half* src = W + (size_t)(n0 + row) * KD + kt * BK + c16 * 8;
            CP_ASYNC16(sw + row * 128 + ((c16 ^ (row & 7)) << 4), src);
        }
    };

    float acc[4][8][4];
    #pragma unroll
    for (int mi = 0; mi < 4; mi++)
        #pragma unroll
        for (int ni = 0; ni < 8; ni++)
            #pragma unroll
            for (int r = 0; r < 4; r++) acc[mi][ni][r] = 0.f;

    // per-lane ldmatrix addressing: lane supplies address for tile (lane>>3)
    const int tl   = lane >> 3;          // 0..3
    const int tr   = lane & 7;           // row within 8-row tile
    const int rsel = (tl & 1) * 8;       // tiles 1,3 -> +8 rows
    const int kh   = tl >> 1;            // tiles 2,3 -> high k-half (+16B)

    uint32_t aRow[4], bRow[4];
    #pragma unroll
    for (int mi = 0; mi < 4; mi++) aRow[mi] = (wm * 64 + mi * 16 + rsel + tr) * 128;
    #pragma unroll
    for (int nj = 0; nj < 4; nj++) bRow[nj] = (wn * 64 + nj * 16 + rsel + tr) * 128;

    auto compute = [&](int s) {
        const uint32_t aB = sb + s * ASTG;
        const uint32_t bB = sb + BOFF + s * BSTG;
        #pragma unroll
        for (int ks = 0; ks < 4; ks++) {
            const uint32_t kcx = (uint32_t)(((ks * 2 + kh) ^ tr) << 4);
            uint32_t a[4][4], bf[4][4];
            #pragma unroll
            for (int mi = 0; mi < 4; mi++)
                LDSM_X4(a[mi][0], a[mi][1], a[mi][2], a[mi][3], aB + aRow[mi] + kcx);
            #pragma unroll
            for (int nj = 0; nj < 4; nj++)
                LDSM_X4(bf[nj][0], bf[nj][1], bf[nj][2], bf[nj][3], bB + bRow[nj] + kcx);
            #pragma unroll
            for (int mi = 0; mi < 4; mi++)
                #pragma unroll
                for (int n8 = 0; n8 < 8; n8++) {
                    const int nj = n8 >> 1, hi = n8 & 1;
                    MMA_F16(acc[mi][n8], a[mi], bf[nj][hi], bf[nj][hi + 2]);
                }
        }
    };

    stage(0); CP_COMMIT();
    stage(1); CP_COMMIT();

    for (int kt = 0; kt < NKT; kt++) {
        CP_WAIT1();
        __syncthreads();
        if (kt + 2 < NKT) stage(kt + 2);
        CP_COMMIT();
        compute(kt % 3);
    }

    // epilogue
    const int gq = lane >> 2, tg = lane & 3;
    #pragma unroll
    for (int mi = 0; mi < 4; mi++) {
        const int r = m0 + wm * 64 + mi * 16 + gq;
        #pragma unroll
        for (int ni = 0; ni < 8; ni++) {
            const int cc = n0 + wn * 64 + ni * 8 + tg * 2;
            const float b0 = __ldg(bias + cc);
            const float b1 = __ldg(bias + cc + 1);
            if constexpr (sizeof(OutT) == 2) {
                __half2* p0 = (__half2*)((__half*)C + (size_t)r * DM + cc);
                __half2* p1 = (__half2*)((__half*)C + (size_t)(r + 8) * DM + cc);
                *p0 = __floats2half2_rn(acc[mi][ni][0] + b0, acc[mi][ni][1] + b1);
                *p1 = __floats2half2_rn(acc[mi][ni][2] + b0, acc[mi][ni][3] + b1);
            } else {
                *(float2*)((float*)C + (size_t)r * DM + cc) =
                    make_float2(acc[mi][ni][0] + b0, acc[mi][ni][1] + b1);
                *(float2*)((float*)C + (size_t)(r + 8) * DM + cc) =
                    make_float2(acc[mi][ni][2] + b0, acc[mi][ni][3] + b1);
            }
        }
    }
}

// ---------------- fp32 -> fp16 conversion (rn) ----------------
__global__ __launch_bounds__(256)
void cvt_h(const float4* __restrict__ in, uint2* __restrict__ out, int n4)
{
    int i  = blockIdx.x * blockDim.x + threadIdx.x;
    int st = gridDim.x * blockDim.x;
    for (; i < n4; i += st) {
        float4 v = in[i];
        __half2 h0 = __floats2half2_rn(v.x, v.y);
        __half2 h1 = __floats2half2_rn(v.z, v.w);
        out[i] = make_uint2(*(uint32_t*)&h0, *(uint32_t*)&h1);
    }
}

// ---------------- per-token head-mixing attention (fp16 I/O, fp32 math) ------
__global__ __launch_bounds__(256)
void head_attn(const __half* __restrict__ qh, const __half* __restrict__ kh,
               const __half* __restrict__ vh, __half* __restrict__ out)
{
    __shared__ float qs[NH][HD + 4];
    __shared__ float ks[NH][HD + 4];
    __shared__ float vs[NH][HD + 4];
    __shared__ float sc[NH][NH + 1];

    const int tok = blockIdx.x;
    const int t   = threadIdx.x;
    const size_t base = (size_t)tok * DM;

    {
        int row = t >> 4;
        int c4  = (t & 15) * 4;                  // half index, 4 halfs per thread
        const __half2* qp = (const __half2*)(qh + base + row * HD + c4);
        const __half2* kp = (const __half2*)(kh + base + row * HD + c4);
        const __half2* vp = (const __half2*)(vh + base + row * HD + c4);
        float2 a0 = __half22float2(qp[0]), a1 = __half22float2(qp[1]);
        float2 b0 = __half22float2(kp[0]), b1 = __half22float2(kp[1]);
        float2 c0 = __half22float2(vp[0]), c1 = __half22float2(vp[1]);
        qs[row][c4] = a0.x; qs[row][c4+1] = a0.y; qs[row][c4+2] = a1.x; qs[row][c4+3] = a1.y;
        ks[row][c4] = b0.x; ks[row][c4+1] = b0.y; ks[row][c4+2] = b1.x; ks[row][c4+3] = b1.y;
        vs[row][c4] = c0.x; vs[row][c4+1] = c0.y; vs[row][c4+2] = c1.x; vs[row][c4+3] = c1.y;
    }
    __syncthreads();

    {
        int h = t >> 4, g = t & 15;
        float s = 0.f;
        #pragma unroll
        for (int d4 = 0; d4 < HD; d4 += 4) {
            float4 a = *(const float4*)&qs[h][d4];
            float4 b = *(const float4*)&ks[g][d4];
            s += a.x * b.x + a.y * b.y + a.z * b.z + a.w * b.w;
        }
        sc[h][g] = s * 0.125f;
    }
    __syncthreads();

    if (t < NH) {
        float m = sc[t][0];
        #pragma unroll
        for (int g = 1; g < NH; g++) m = fmaxf(m, sc[t][g]);
        float e[NH], sum = 0.f;
        #pragma unroll
        for (int g = 0; g < NH; g++) { e[g] = __expf(sc[t][g] - m); sum += e[g]; }
        float inv = 1.f / sum;
        #pragma unroll
        for (int g = 0; g < NH; g++) sc[t][g] = e[g] * inv;
    }
    __syncthreads();

    {
        int h  = t >> 4;
        int d4 = (t & 15) * 4;
        float4 acc = make_float4(0.f, 0.f, 0.f, 0.f);
        #pragma unroll
        for (int g = 0; g < NH; g++) {
            float w = sc[h][g];
            float4 vv = *(const float4*)&vs[g][d4];
            acc.x += w * vv.x; acc.y += w * vv.y;
            acc.z += w * vv.z; acc.w += w * vv.w;
        }
        __half2 h0 = __floats2half2_rn(acc.x, acc.y);
        __half2 h1 = __floats2half2_rn(acc.z, acc.w);
        *(uint2*)(out + base + h * HD + d4) = make_uint2(*(uint32_t*)&h0, *(uint32_t*)&h1);
    }
}

// ---------------------------------------------------------------------------
extern "C" void kernel_launch(void* const* d_in, const int* in_sizes, int n_in,
                              void* d_out, int out_size)
{
    const float* q  = (const float*)d_in[0];
    const float* k  = (const float*)d_in[1];
    const float* v  = (const float*)d_in[2];
    const float* Wq = (const float*)d_in[3];
    const float* bq = (const float*)d_in[4];
    const float* Wk = (const float*)d_in[5];
    const float* bk = (const float*)d_in[6];
    const float* Wv = (const float*)d_in[7];
    const float* bv = (const float*)d_in[8];
    const float* Wo = (const float*)d_in[9];
    const float* bo = (const float*)d_in[10];
    float* out = (float*)d_out;

    __half *hq, *hk, *hv, *hWq, *hWk, *hWv, *hWo, *qh, *kh, *vh, *att;
    cudaGetSymbolAddress((void**)&hq,  g_hq);
    cudaGetSymbolAddress((void**)&hk,  g_hk);
    cudaGetSymbolAddress((void**)&hv,  g_hv);
    cudaGetSymbolAddress((void**)&hWq, g_hWq);
    cudaGetSymbolAddress((void**)&hWk, g_hWk);
    cudaGetSymbolAddress((void**)&hWv, g_hWv);
    cudaGetSymbolAddress((void**)&hWo, g_hWo);
    cudaGetSymbolAddress((void**)&qh,  g_qh);
    cudaGetSymbolAddress((void**)&kh,  g_kh);
    cudaGetSymbolAddress((void**)&vh,  g_vh);
    cudaGetSymbolAddress((void**)&att, g_att);

    cudaFuncSetAttribute(gemm_h<__half>, cudaFuncAttributeMaxDynamicSharedMemorySize, GEMM_SMEM);
    cudaFuncSetAttribute(gemm_h<float>,  cudaFuncAttributeMaxDynamicSharedMemorySize, GEMM_SMEM);

    const int n4_in = NTOK * DM / 4;
    const int n4_w  = DM * DM / 4;
    cvt_h<<<2048, 256>>>((const float4*)q,  (uint2*)hq,  n4_in);
    cvt_h<<<2048, 256>>>((const float4*)k,  (uint2*)hk,  n4_in);
    cvt_h<<<2048, 256>>>((const float4*)v,  (uint2*)hv,  n4_in);
    cvt_h<<<1024, 256>>>((const float4*)Wq, (uint2*)hWq, n4_w);
    cvt_h<<<1024, 256>>>((const float4*)Wk, (uint2*)hWk, n4_w);
    cvt_h<<<1024, 256>>>((const float4*)Wv, (uint2*)hWv, n4_w);
    cvt_h<<<1024, 256>>>((const float4*)Wo, (uint2*)hWo, n4_w);

    dim3 gg(DM / BN, NTOK / BM);   // (4, 128)
    gemm_h<__half><<<gg, 256, GEMM_SMEM>>>(hq,  hWq, bq, qh);
    gemm_h<__half><<<gg, 256, GEMM_SMEM>>>(hk,  hWk, bk, kh);
    gemm_h<__half><<<gg, 256, GEMM_SMEM>>>(hv,  hWv, bv, vh);
    head_attn<<<NTOK, 256>>>(qh, kh, vh, att);
    gemm_h<float><<<gg, 256, GEMM_SMEM>>>(att, hWo, bo, out);
}

// round 6
// speedup vs baseline: 2.4265x; 1.0739x over previous
#include <cuda_runtime.h>
#include <cuda_fp16.h>
#include <cstdint>

#define NTOK 16384
#define DM   1024
#define NH   16
#define HD   64
#define KD   1024

// ---------------- scratch (fp16 copies + intermediates) ----------------
__device__ __half g_hq [(size_t)NTOK * DM];
__device__ __half g_hk [(size_t)NTOK * DM];
__device__ __half g_hv [(size_t)NTOK * DM];
__device__ __half g_hWq[(size_t)DM * DM];
__device__ __half g_hWk[(size_t)DM * DM];
__device__ __half g_hWv[(size_t)DM * DM];
__device__ __half g_hWo[(size_t)DM * DM];
__device__ __half g_qh [(size_t)NTOK * DM];
__device__ __half g_kh [(size_t)NTOK * DM];
__device__ __half g_vh [(size_t)NTOK * DM];
__device__ __half g_att[(size_t)NTOK * DM];

__device__ __forceinline__ uint32_t smem_u32(const void* p) {
    uint32_t a;
    asm("{ .reg .u64 t; cvta.to.shared.u64 t, %1; cvt.u32.u64 %0, t; }" : "=r"(a) : "l"(p));
    return a;
}

// ---------------------------------------------------------------------------
// GEMM: C[M,1024] = A[M,1024] @ W[1024,1024]^T + bias   (fp16 in, fp32 acc)
// BM=128 BN=256 BK=64, 256 thr, 8 warps (2x4), warp tile 64x64.
// 4-stage cp.async pipeline; XOR-swizzled 128B rows; ldmatrix.x4 frags with
// software double-buffering of fragments.
// ---------------------------------------------------------------------------
#define BM 128
#define BN 256
#define BK 64
#define NKT (KD / BK)            // 16
#define NST 4
#define ASTG 16384               // bytes per A stage (128 rows x 128B)
#define BSTG 32768               // bytes per B stage (256 rows x 128B)
#define BOFF (NST * ASTG)        // 65536
#define GEMM_SMEM (NST * (ASTG + BSTG))   // 196608

#define LDSM_X4(r0, r1, r2, r3, addr)                                           \
    asm volatile("ldmatrix.sync.aligned.m8n8.x4.shared.b16 {%0,%1,%2,%3}, [%4];" \
                 : "=r"(r0), "=r"(r1), "=r"(r2), "=r"(r3) : "r"(addr))

#define MMA_F16(acc, a, b0, b1)                                                 \
    asm volatile("mma.sync.aligned.m16n8k16.row.col.f32.f16.f16.f32 "           \
                 "{%0,%1,%2,%3}, {%4,%5,%6,%7}, {%8,%9}, {%0,%1,%2,%3};\n"      \
                 : "+f"((acc)[0]), "+f"((acc)[1]), "+f"((acc)[2]), "+f"((acc)[3]) \
                 : "r"((a)[0]), "r"((a)[1]), "r"((a)[2]), "r"((a)[3]),          \
                   "r"(b0), "r"(b1))

#define CP_ASYNC16(dst, src) \
    asm volatile("cp.async.cg.shared.global [%0], [%1], 16;" :: "r"(dst), "l"(src))
#define CP_COMMIT() asm volatile("cp.async.commit_group;")
#define CP_WAIT2()  asm volatile("cp.async.wait_group 2;")

template <typename OutT>
__global__ __launch_bounds__(256, 1)
void gemm_h(const __half* __restrict__ A, const __half* __restrict__ W,
            const float* __restrict__ bias, OutT* __restrict__ C)
{
    extern __shared__ char smem[];
    const uint32_t sb = smem_u32(smem);

    const int t    = threadIdx.x;
    const int warp = t >> 5;
    const int lane = t & 31;
    const int wm   = warp >> 2;          // 0..1
    const int wn   = warp & 3;           // 0..3
    const int m0   = blockIdx.y * BM;
    const int n0   = blockIdx.x * BN;

    auto stage = [&](int kt) {
        const int s = kt & (NST - 1);
        const uint32_t sa = sb + s * ASTG;
        const uint32_t sw = sb + BOFF + s * BSTG;
        #pragma unroll
        for (int i = 0; i < 4; i++) {            // A: 1024 16B chunks
            int id  = t + i * 256;
            int row = id >> 3, c16 = id & 7;
            const __half* src = A + (size_t)(m0 + row) * KD + kt * BK + c16 * 8;
            CP_ASYNC16(sa + row * 128 + ((c16 ^ (row & 7)) << 4), src);
        }
        #pragma unroll
        for (int i = 0; i < 8; i++) {            // B: 2048 16B chunks
            int id  = t + i * 256;
            int row = id >> 3, c16 = id & 7;
            const __half* src = W + (size_t)(n0 + row) * KD + kt * BK + c16 * 8;
            CP_ASYNC16(sw + row * 128 + ((c16 ^ (row & 7)) << 4), src);
        }
    };

    float acc[4][8][4];
    #pragma unroll
    for (int mi = 0; mi < 4; mi++)
        #pragma unroll
        for (int ni = 0; ni < 8; ni++)
            #pragma unroll
            for (int r = 0; r < 4; r++) acc[mi][ni][r] = 0.f;

    // per-lane ldmatrix addressing: lane supplies address for tile (lane>>3)
    const int tl   = lane >> 3;          // 0..3
    const int tr   = lane & 7;           // row within 8-row tile
    const int rsel = (tl & 1) * 8;       // tiles 1,3 -> +8 rows
    const int khh  = tl >> 1;            // tiles 2,3 -> high k-half (+16B)

    uint32_t aRow[4], bRow[4];
    #pragma unroll
    for (int mi = 0; mi < 4; mi++) aRow[mi] = (wm * 64 + mi * 16 + rsel + tr) * 128;
    #pragma unroll
    for (int nj = 0; nj < 4; nj++) bRow[nj] = (wn * 64 + nj * 16 + rsel + tr) * 128;

    auto ldfr = [&](uint32_t aB, uint32_t bB, int ks,
                    uint32_t (*a)[4], uint32_t (*bf)[4]) {
        const uint32_t kcx = (uint32_t)(((ks * 2 + khh) ^ tr) << 4);
        #pragma unroll
        for (int mi = 0; mi < 4; mi++)
            LDSM_X4(a[mi][0], a[mi][1], a[mi][2], a[mi][3], aB + aRow[mi] + kcx);
        #pragma unroll
        for (int nj = 0; nj < 4; nj++)
            LDSM_X4(bf[nj][0], bf[nj][1], bf[nj][2], bf[nj][3], bB + bRow[nj] + kcx);
    };

    auto compute = [&](int s) {
        const uint32_t aB = sb + s * ASTG;
        const uint32_t bB = sb + BOFF + s * BSTG;
        uint32_t a[2][4][4], bf[2][4][4];
        ldfr(aB, bB, 0, a[0], bf[0]);
        #pragma unroll
        for (int ks = 0; ks < 4; ks++) {
            const int cur = ks & 1;
            if (ks < 3) ldfr(aB, bB, ks + 1, a[cur ^ 1], bf[cur ^ 1]);
            #pragma unroll
            for (int mi = 0; mi < 4; mi++)
                #pragma unroll
                for (int n8 = 0; n8 < 8; n8++) {
                    const int nj = n8 >> 1, hi = n8 & 1;
                    MMA_F16(acc[mi][n8], a[cur][mi], bf[cur][nj][hi], bf[cur][nj][hi + 2]);
                }
        }
    };

    stage(0); CP_COMMIT();
    stage(1); CP_COMMIT();
    stage(2); CP_COMMIT();

    for (int kt = 0; kt < NKT; kt++) {
        CP_WAIT2();
        __syncthreads();
        if (kt + 3 < NKT) stage(kt + 3);
        CP_COMMIT();
        compute(kt & (NST - 1));
    }

    // epilogue
    const int gq = lane >> 2, tg = lane & 3;
    #pragma unroll
    for (int mi = 0; mi < 4; mi++) {
        const int r = m0 + wm * 64 + mi * 16 + gq;
        #pragma unroll
        for (int ni = 0; ni < 8; ni++) {
            const int cc = n0 + wn * 64 + ni * 8 + tg * 2;
            const float b0 = __ldg(bias + cc);
            const float b1 = __ldg(bias + cc + 1);
            if constexpr (sizeof(OutT) == 2) {
                __half2* p0 = (__half2*)((__half*)C + (size_t)r * DM + cc);
                __half2* p1 = (__half2*)((__half*)C + (size_t)(r + 8) * DM + cc);
                *p0 = __floats2half2_rn(acc[mi][ni][0] + b0, acc[mi][ni][1] + b1);
                *p1 = __floats2half2_rn(acc[mi][ni][2] + b0, acc[mi][ni][3] + b1);
            } else {
                *(float2*)((float*)C + (size_t)r * DM + cc) =
                    make_float2(acc[mi][ni][0] + b0, acc[mi][ni][1] + b1);
                *(float2*)((float*)C + (size_t)(r + 8) * DM + cc) =
                    make_float2(acc[mi][ni][2] + b0, acc[mi][ni][3] + b1);
            }
        }
    }
}

// ---------------- fp32 -> fp16 conversions (batched, MLP=4) ----------------
__global__ __launch_bounds__(256)
void cvt3(const float4* __restrict__ i0, uint2* __restrict__ o0,
          const float4* __restrict__ i1, uint2* __restrict__ o1,
          const float4* __restrict__ i2, uint2* __restrict__ o2)
{
    const float4* in;
    uint2* out;
    if (blockIdx.y == 0)      { in = i0; out = o0; }
    else if (blockIdx.y == 1) { in = i1; out = o1; }
    else                      { in = i2; out = o2; }
    int base = blockIdx.x * 1024 + threadIdx.x;
    float4 v[4];
    #pragma unroll
    for (int j = 0; j < 4; j++) v[j] = in[base + j * 256];
    #pragma unroll
    for (int j = 0; j < 4; j++) {
        __half2 h0 = __floats2half2_rn(v[j].x, v[j].y);
        __half2 h1 = __floats2half2_rn(v[j].z, v[j].w);
        out[base + j * 256] = make_uint2(*(uint32_t*)&h0, *(uint32_t*)&h1);
    }
}

__global__ __launch_bounds__(256)
void cvt4(const float4* __restrict__ i0, uint2* __restrict__ o0,
          const float4* __restrict__ i1, uint2* __restrict__ o1,
          const float4* __restrict__ i2, uint2* __restrict__ o2,
          const float4* __restrict__ i3, uint2* __restrict__ o3)
{
    const float4* in;
    uint2* out;
    if (blockIdx.y == 0)      { in = i0; out = o0; }
    else if (blockIdx.y == 1) { in = i1; out = o1; }
    else if (blockIdx.y == 2) { in = i2; out = o2; }
    else                      { in = i3; out = o3; }
    int base = blockIdx.x * 1024 + threadIdx.x;
    float4 v[4];
    #pragma unroll
    for (int j = 0; j < 4; j++) v[j] = in[base + j * 256];
    #pragma unroll
    for (int j = 0; j < 4; j++) {
        __half2 h0 = __floats2half2_rn(v[j].x, v[j].y);
        __half2 h1 = __floats2half2_rn(v[j].z, v[j].w);
        out[base + j * 256] = make_uint2(*(uint32_t*)&h0, *(uint32_t*)&h1);
    }
}

// ---------------- per-token head-mixing attention ----------------
// fp16 smem (no extra rounding: inputs already fp16), fp32 math.
#define HROW 34   // half2 words per smem row (32 data + 2 pad); 8B-aligned rows

__global__ __launch_bounds__(256)
void head_attn(const __half* __restrict__ qh, const __half* __restrict__ kh,
               const __half* __restrict__ vh, __half* __restrict__ out)
{
    __shared__ uint32_t qs[NH * HROW];   // half2 elements
    __shared__ uint32_t ks[NH * HROW];
    __shared__ uint32_t vs[NH * HROW];
    __shared__ float    sc[NH][NH + 1];

    const int tok = blockIdx.x;
    const int t   = threadIdx.x;
    const size_t base = (size_t)tok * DM;

    {
        int row = t >> 4;                 // 0..15
        int c   = t & 15;                 // uint2 chunk (4 halfs)
        const uint2* qp = (const uint2*)(qh + base + row * HD) + c;
        const uint2* kp = (const uint2*)(kh + base + row * HD) + c;
        const uint2* vp = (const uint2*)(vh + base + row * HD) + c;
        *(uint2*)&qs[row * HROW + c * 2] = *qp;
        *(uint2*)&ks[row * HROW + c * 2] = *kp;
        *(uint2*)&vs[row * HROW + c * 2] = *vp;
    }
    __syncthreads();

    {
        int h = t >> 4, g = t & 15;
        float s = 0.f;
        #pragma unroll
        for (int c = 0; c < 16; c++) {    // 4 halfs per step
            uint2 qa = *(const uint2*)&qs[h * HROW + c * 2];
            uint2 ka = *(const uint2*)&ks[g * HROW + c * 2];
            float2 q0 = __half22float2(*(__half2*)&qa.x);
            float2 q1 = __half22float2(*(__half2*)&qa.y);
            float2 k0 = __half22float2(*(__half2*)&ka.x);
            float2 k1 = __half22float2(*(__half2*)&ka.y);
            s += q0.x * k0.x + q0.y * k0.y + q1.x * k1.x + q1.y * k1.y;
        }
        sc[h][g] = s * 0.125f;
    }
    __syncthreads();

    if (t < NH) {
        float m = sc[t][0];
        #pragma unroll
        for (int g = 1; g < NH; g++) m = fmaxf(m, sc[t][g]);
        float e[NH], sum = 0.f;
        #pragma unroll
        for (int g = 0; g < NH; g++) { e[g] = __expf(sc[t][g] - m); sum += e[g]; }
        float inv = 1.f / sum;
        #pragma unroll
        for (int g = 0; g < NH; g++) sc[t][g] = e[g] * inv;
    }
    __syncthreads();

    {
        int h = t >> 4;
        int c = t & 15;                   // output chunk of 4 halfs
        float4 acc = make_float4(0.f, 0.f, 0.f, 0.f);
        #pragma unroll
        for (int g = 0; g < NH; g++) {
            float w = sc[h][g];
            uint2 va = *(const uint2*)&vs[g * HROW + c * 2];
            float2 v0 = __half22float2(*(__half2*)&va.x);
            float2 v1 = __half22float2(*(__half2*)&va.y);
            acc.x += w * v0.x; acc.y += w * v0.y;
            acc.z += w * v1.x; acc.w += w * v1.y;
        }
        __half2 h0 = __floats2half2_rn(acc.x, acc.y);
        __half2 h1 = __floats2half2_rn(acc.z, acc.w);
        *(uint2*)(out + base + h * HD + c * 4) =
            make_uint2(*(uint32_t*)&h0, *(uint32_t*)&h1);
    }
}

// ---------------------------------------------------------------------------
extern "C" void kernel_launch(void* const* d_in, const int* in_sizes, int n_in,
                              void* d_out, int out_size)
{
    const float* q  = (const float*)d_in[0];
    const float* k  = (const float*)d_in[1];
    const float* v  = (const float*)d_in[2];
    const float* Wq = (const float*)d_in[3];
    const float* bq = (const float*)d_in[4];
    const float* Wk = (const float*)d_in[5];
    const float* bk = (const float*)d_in[6];
    const float* Wv = (const float*)d_in[7];
    const float* bv = (const float*)d_in[8];
    const float* Wo = (const float*)d_in[9];
    const float* bo = (const float*)d_in[10];
    float* out = (float*)d_out;

    __half *hq, *hk, *hv, *hWq, *hWk, *hWv, *hWo, *qh, *kh, *vh, *att;
    cudaGetSymbolAddress((void**)&hq,  g_hq);
    cudaGetSymbolAddress((void**)&hk,  g_hk);
    cudaGetSymbolAddress((void**)&hv,  g_hv);
    cudaGetSymbolAddress((void**)&hWq, g_hWq);
    cudaGetSymbolAddress((void**)&hWk, g_hWk);
    cudaGetSymbolAddress((void**)&hWv, g_hWv);
    cudaGetSymbolAddress((void**)&hWo, g_hWo);
    cudaGetSymbolAddress((void**)&qh,  g_qh);
    cudaGetSymbolAddress((void**)&kh,  g_kh);
    cudaGetSymbolAddress((void**)&vh,  g_vh);
    cudaGetSymbolAddress((void**)&att, g_att);

    cudaFuncSetAttribute(gemm_h<__half>, cudaFuncAttributeMaxDynamicSharedMemorySize, GEMM_SMEM);
    cudaFuncSetAttribute(gemm_h<float>,  cudaFuncAttributeMaxDynamicSharedMemorySize, GEMM_SMEM);

    // conversions: q,k,v (4M float4 each) and 4 weights (256K float4 each)
    cvt3<<<dim3(4096, 3), 256>>>((const float4*)q, (uint2*)hq,
                                 (const float4*)k, (uint2*)hk,
                                 (const float4*)v, (uint2*)hv);
    cvt4<<<dim3(256, 4), 256>>>((const float4*)Wq, (uint2*)hWq,
                                (const float4*)Wk, (uint2*)hWk,
                                (const float4*)Wv, (uint2*)hWv,
                                (const float4*)Wo, (uint2*)hWo);

    dim3 gg(DM / BN, NTOK / BM);   // (4, 128)
    gemm_h<__half><<<gg, 256, GEMM_SMEM>>>(hq,  hWq, bq, qh);
    gemm_h<__half><<<gg, 256, GEMM_SMEM>>>(hk,  hWk, bk, kh);
    gemm_h<__half><<<gg, 256, GEMM_SMEM>>>(hv,  hWv, bv, vh);
    head_attn<<<NTOK, 256>>>(qh, kh, vh, att);
    gemm_h<float><<<gg, 256, GEMM_SMEM>>>(att, hWo, bo, out);
}

// round 7
// speedup vs baseline: 2.4739x; 1.0195x over previous
#include <cuda_runtime.h>
#include <cuda_fp16.h>
#include <cstdint>

#define NTOK 16384
#define DM   1024
#define NH   16
#define HD   64
#define KD   1024

// ---------------- scratch (fp16 copies + intermediates) ----------------
__device__ __half g_hq [(size_t)NTOK * DM];
__device__ __half g_hk [(size_t)NTOK * DM];
__device__ __half g_hv [(size_t)NTOK * DM];
__device__ __half g_hWq[(size_t)DM * DM];
__device__ __half g_hWk[(size_t)DM * DM];
__device__ __half g_hWv[(size_t)DM * DM];
__device__ __half g_hWo[(size_t)DM * DM];
__device__ __half g_qh [(size_t)NTOK * DM];
__device__ __half g_kh [(size_t)NTOK * DM];
__device__ __half g_vh [(size_t)NTOK * DM];
__device__ __half g_att[(size_t)NTOK * DM];

__device__ __forceinline__ uint32_t smem_u32(const void* p) {
    uint32_t a;
    asm("{ .reg .u64 t; cvta.to.shared.u64 t, %1; cvt.u32.u64 %0, t; }" : "=r"(a) : "l"(p));
    return a;
}

// ---------------------------------------------------------------------------
// GEMM: C[M,1024] = A[M,1024] @ W[1024,1024]^T + bias   (fp16 in, fp32 acc)
// BM=128 BN=256 BK=64, 512 thr, 16 warps (4x4), warp tile 32x64.
// 4 warps/SMSP for tensor-pipe latency hiding; 4-stage cp.async pipeline;
// XOR-swizzled 128B rows; ldmatrix.x4 fragments (single-buffered).
// ---------------------------------------------------------------------------
#define BM 128
#define BN 256
#define BK 64
#define NKT (KD / BK)            // 16
#define NST 4
#define ASTG 16384               // bytes per A stage (128 rows x 128B)
#define BSTG 32768               // bytes per B stage (256 rows x 128B)
#define BOFF (NST * ASTG)        // 65536
#define GEMM_SMEM (NST * (ASTG + BSTG))   // 196608
#define NTHR 512

#define LDSM_X4(r0, r1, r2, r3, addr)                                           \
    asm volatile("ldmatrix.sync.aligned.m8n8.x4.shared.b16 {%0,%1,%2,%3}, [%4];" \
                 : "=r"(r0), "=r"(r1), "=r"(r2), "=r"(r3) : "r"(addr))

#define MMA_F16(acc, a, b0, b1)                                                 \
    asm volatile("mma.sync.aligned.m16n8k16.row.col.f32.f16.f16.f32 "           \
                 "{%0,%1,%2,%3}, {%4,%5,%6,%7}, {%8,%9}, {%0,%1,%2,%3};\n"      \
                 : "+f"((acc)[0]), "+f"((acc)[1]), "+f"((acc)[2]), "+f"((acc)[3]) \
                 : "r"((a)[0]), "r"((a)[1]), "r"((a)[2]), "r"((a)[3]),          \
                   "r"(b0), "r"(b1))

#define CP_ASYNC16(dst, src) \
    asm volatile("cp.async.cg.shared.global [%0], [%1], 16;" :: "r"(dst), "l"(src))
#define CP_COMMIT() asm volatile("cp.async.commit_group;")
#define CP_WAIT2()  asm volatile("cp.async.wait_group 2;")

template <typename OutT>
__global__ __launch_bounds__(NTHR, 1)
void gemm_h(const __half* __restrict__ A, const __half* __restrict__ W,
            const float* __restrict__ bias, OutT* __restrict__ C)
{
    extern __shared__ char smem[];
    const uint32_t sb = smem_u32(smem);

    const int t    = threadIdx.x;
    const int warp = t >> 5;
    const int lane = t & 31;
    const int wm   = warp >> 2;          // 0..3  (M)
    const int wn   = warp & 3;           // 0..3  (N)
    const int m0   = blockIdx.y * BM;
    const int n0   = blockIdx.x * BN;

    auto stage = [&](int kt) {
        const int s = kt & (NST - 1);
        const uint32_t sa = sb + s * ASTG;
        const uint32_t sw = sb + BOFF + s * BSTG;
        #pragma unroll
        for (int i = 0; i < 2; i++) {            // A: 1024 16B chunks
            int id  = t + i * NTHR;
            int row = id >> 3, c16 = id & 7;
            const __half* src = A + (size_t)(m0 + row) * KD + kt * BK + c16 * 8;
            CP_ASYNC16(sa + row * 128 + ((c16 ^ (row & 7)) << 4), src);
        }
        #pragma unroll
        for (int i = 0; i < 4; i++) {            // B: 2048 16B chunks
            int id  = t + i * NTHR;
            int row = id >> 3, c16 = id & 7;
            const __half* src = W + (size_t)(n0 + row) * KD + kt * BK + c16 * 8;
            CP_ASYNC16(sw + row * 128 + ((c16 ^ (row & 7)) << 4), src);
        }
    };

    float acc[2][8][4];
    #pragma unroll
    for (int mi = 0; mi < 2; mi++)
        #pragma unroll
        for (int ni = 0; ni < 8; ni++)
            #pragma unroll
            for (int r = 0; r < 4; r++) acc[mi][ni][r] = 0.f;

    // per-lane ldmatrix addressing: lane supplies address for tile (lane>>3)
    const int tl   = lane >> 3;          // 0..3
    const int tr   = lane & 7;           // row within 8-row tile
    const int rsel = (tl & 1) * 8;       // tiles 1,3 -> +8 rows
    const int khh  = tl >> 1;            // tiles 2,3 -> high k-half

    uint32_t aRow[2], bRow[4];
    #pragma unroll
    for (int mi = 0; mi < 2; mi++) aRow[mi] = (wm * 32 + mi * 16 + rsel + tr) * 128;
    #pragma unroll
    for (int nj = 0; nj < 4; nj++) bRow[nj] = (wn * 64 + nj * 16 + rsel + tr) * 128;

    auto compute = [&](int s) {
        const uint32_t aB = sb + s * ASTG;
        const uint32_t bB = sb + BOFF + s * BSTG;
        #pragma unroll
        for (int ks = 0; ks < 4; ks++) {
            const uint32_t kcx = (uint32_t)(((ks * 2 + khh) ^ tr) << 4);
            uint32_t a[2][4], bf[4][4];
            #pragma unroll
            for (int mi = 0; mi < 2; mi++)
                LDSM_X4(a[mi][0], a[mi][1], a[mi][2], a[mi][3], aB + aRow[mi] + kcx);
            #pragma unroll
            for (int nj = 0; nj < 4; nj++)
                LDSM_X4(bf[nj][0], bf[nj][1], bf[nj][2], bf[nj][3], bB + bRow[nj] + kcx);
            #pragma unroll
            for (int mi = 0; mi < 2; mi++)
                #pragma unroll
                for (int n8 = 0; n8 < 8; n8++) {
                    const int nj = n8 >> 1, hi = n8 & 1;
                    MMA_F16(acc[mi][n8], a[mi], bf[nj][hi], bf[nj][hi + 2]);
                }
        }
    };

    stage(0); CP_COMMIT();
    stage(1); CP_COMMIT();
    stage(2); CP_COMMIT();

    for (int kt = 0; kt < NKT; kt++) {
        CP_WAIT2();
        __syncthreads();
        if (kt + 3 < NKT) stage(kt + 3);
        CP_COMMIT();
        compute(kt & (NST - 1));
    }

    // epilogue
    const int gq = lane >> 2, tg = lane & 3;
    #pragma unroll
    for (int mi = 0; mi < 2; mi++) {
        const int r = m0 + wm * 32 + mi * 16 + gq;
        #pragma unroll
        for (int ni = 0; ni < 8; ni++) {
            const int cc = n0 + wn * 64 + ni * 8 + tg * 2;
            const float b0 = __ldg(bias + cc);
            const float b1 = __ldg(bias + cc + 1);
            if constexpr (sizeof(OutT) == 2) {
                __half2* p0 = (__half2*)((__half*)C + (size_t)r * DM + cc);
                __half2* p1 = (__half2*)((__half*)C + (size_t)(r + 8) * DM + cc);
                *p0 = __floats2half2_rn(acc[mi][ni][0] + b0, acc[mi][ni][1] + b1);
                *p1 = __floats2half2_rn(acc[mi][ni][2] + b0, acc[mi][ni][3] + b1);
            } else {
                *(float2*)((float*)C + (size_t)r * DM + cc) =
                    make_float2(acc[mi][ni][0] + b0, acc[mi][ni][1] + b1);
                *(float2*)((float*)C + (size_t)(r + 8) * DM + cc) =
                    make_float2(acc[mi][ni][2] + b0, acc[mi][ni][3] + b1);
            }
        }
    }
}

// ---------------- fp32 -> fp16 conversions (batched, MLP=4) ----------------
__global__ __launch_bounds__(256)
void cvt3(const float4* __restrict__ i0, uint2* __restrict__ o0,
          const float4* __restrict__ i1, uint2* __restrict__ o1,
          const float4* __restrict__ i2, uint2* __restrict__ o2)
{
    const float4* in;
    uint2* out;
    if (blockIdx.y == 0)      { in = i0; out = o0; }
    else if (blockIdx.y == 1) { in = i1; out = o1; }
    else                      { in = i2; out = o2; }
    int base = blockIdx.x * 1024 + threadIdx.x;
    float4 v[4];
    #pragma unroll
    for (int j = 0; j < 4; j++) v[j] = in[base + j * 256];
    #pragma unroll
    for (int j = 0; j < 4; j++) {
        __half2 h0 = __floats2half2_rn(v[j].x, v[j].y);
        __half2 h1 = __floats2half2_rn(v[j].z, v[j].w);
        out[base + j * 256] = make_uint2(*(uint32_t*)&h0, *(uint32_t*)&h1);
    }
}

__global__ __launch_bounds__(256)
void cvt4(const float4* __restrict__ i0, uint2* __restrict__ o0,
          const float4* __restrict__ i1, uint2* __restrict__ o1,
          const float4* __restrict__ i2, uint2* __restrict__ o2,
          const float4* __restrict__ i3, uint2* __restrict__ o3)
{
    const float4* in;
    uint2* out;
    if (blockIdx.y == 0)      { in = i0; out = o0; }
    else if (blockIdx.y == 1) { in = i1; out = o1; }
    else if (blockIdx.y == 2) { in = i2; out = o2; }
    else                      { in = i3; out = o3; }
    int base = blockIdx.x * 1024 + threadIdx.x;
    float4 v[4];
    #pragma unroll
    for (int j = 0; j < 4; j++) v[j] = in[base + j * 256];
    #pragma unroll
    for (int j = 0; j < 4; j++) {
        __half2 h0 = __floats2half2_rn(v[j].x, v[j].y);
        __half2 h1 = __floats2half2_rn(v[j].z, v[j].w);
        out[base + j * 256] = make_uint2(*(uint32_t*)&h0, *(uint32_t*)&h1);
    }
}

// ---------------- per-token head-mixing attention ----------------
// fp16 smem (no extra rounding: inputs already fp16), fp32 math.
#define HROW 34   // half2 words per smem row (32 data + 2 pad)

__global__ __launch_bounds__(256)
void head_attn(const __half* __restrict__ qh, const __half* __restrict__ kh,
               const __half* __restrict__ vh, __half* __restrict__ out)
{
    __shared__ uint32_t qs[NH * HROW];
    __shared__ uint32_t ks[NH * HROW];
    __shared__ uint32_t vs[NH * HROW];
    __shared__ float    sc[NH][NH + 1];

    const int tok = blockIdx.x;
    const int t   = threadIdx.x;
    const size_t base = (size_t)tok * DM;

    {
        int row = t >> 4;
        int c   = t & 15;
        const uint2* qp = (const uint2*)(qh + base + row * HD) + c;
        const uint2* kp = (const uint2*)(kh + base + row * HD) + c;
        const uint2* vp = (const uint2*)(vh + base + row * HD) + c;
        *(uint2*)&qs[row * HROW + c * 2] = *qp;
        *(uint2*)&ks[row * HROW + c * 2] = *kp;
        *(uint2*)&vs[row * HROW + c * 2] = *vp;
    }
    __syncthreads();

    {
        int h = t >> 4, g = t & 15;
        float s = 0.f;
        #pragma unroll
        for (int c = 0; c < 16; c++) {
            uint2 qa = *(const uint2*)&qs[h * HROW + c * 2];
            uint2 ka = *(const uint2*)&ks[g * HROW + c * 2];
            float2 q0 = __half22float2(*(__half2*)&qa.x);
            float2 q1 = __half22float2(*(__half2*)&qa.y);
            float2 k0 = __half22float2(*(__half2*)&ka.x);
            float2 k1 = __half22float2(*(__half2*)&ka.y);
            s += q0.x * k0.x + q0.y * k0.y + q1.x * k1.x + q1.y * k1.y;
        }
        sc[h][g] = s * 0.125f;
    }
    __syncthreads();

    if (t < NH) {
        float m = sc[t][0];
        #pragma unroll
        for (int g = 1; g < NH; g++) m = fmaxf(m, sc[t][g]);
        float e[NH], sum = 0.f;
        #pragma unroll
        for (int g = 0; g < NH; g++) { e[g] = __expf(sc[t][g] - m); sum += e[g]; }
        float inv = 1.f / sum;
        #pragma unroll
        for (int g = 0; g < NH; g++) sc[t][g] = e[g] * inv;
    }
    __syncthreads();

    {
        int h = t >> 4;
        int c = t & 15;
        float4 acc = make_float4(0.f, 0.f, 0.f, 0.f);
        #pragma unroll
        for (int g = 0; g < NH; g++) {
            float w = sc[h][g];
            uint2 va = *(const uint2*)&vs[g * HROW + c * 2];
            float2 v0 = __half22float2(*(__half2*)&va.x);
            float2 v1 = __half22float2(*(__half2*)&va.y);
            acc.x += w * v0.x; acc.y += w * v0.y;
            acc.z += w * v1.x; acc.w += w * v1.y;
        }
        __half2 h0 = __floats2half2_rn(acc.x, acc.y);
        __half2 h1 = __floats2half2_rn(acc.z, acc.w);
        *(uint2*)(out + base + h * HD + c * 4) =
            make_uint2(*(uint32_t*)&h0, *(uint32_t*)&h1);
    }
}

// ---------------------------------------------------------------------------
extern "C" void kernel_launch(void* const* d_in, const int* in_sizes, int n_in,
                              void* d_out, int out_size)
{
    const float* q  = (const float*)d_in[0];
    const float* k  = (const float*)d_in[1];
    const float* v  = (const float*)d_in[2];
    const float* Wq = (const float*)d_in[3];
    const float* bq = (const float*)d_in[4];
    const float* Wk = (const float*)d_in[5];
    const float* bk = (const float*)d_in[6];
    const float* Wv = (const float*)d_in[7];
    const float* bv = (const float*)d_in[8];
    const float* Wo = (const float*)d_in[9];
    const float* bo = (const float*)d_in[10];
    float* out = (float*)d_out;

    __half *hq, *hk, *hv, *hWq, *hWk, *hWv, *hWo, *qh, *kh, *vh, *att;
    cudaGetSymbolAddress((void**)&hq,  g_hq);
    cudaGetSymbolAddress((void**)&hk,  g_hk);
    cudaGetSymbolAddress((void**)&hv,  g_hv);
    cudaGetSymbolAddress((void**)&hWq, g_hWq);
    cudaGetSymbolAddress((void**)&hWk, g_hWk);
    cudaGetSymbolAddress((void**)&hWv, g_hWv);
    cudaGetSymbolAddress((void**)&hWo, g_hWo);
    cudaGetSymbolAddress((void**)&qh,  g_qh);
    cudaGetSymbolAddress((void**)&kh,  g_kh);
    cudaGetSymbolAddress((void**)&vh,  g_vh);
    cudaGetSymbolAddress((void**)&att, g_att);

    cudaFuncSetAttribute(gemm_h<__half>, cudaFuncAttributeMaxDynamicSharedMemorySize, GEMM_SMEM);
    cudaFuncSetAttribute(gemm_h<float>,  cudaFuncAttributeMaxDynamicSharedMemorySize, GEMM_SMEM);

    cvt3<<<dim3(4096, 3), 256>>>((const float4*)q, (uint2*)hq,
                                 (const float4*)k, (uint2*)hk,
                                 (const float4*)v, (uint2*)hv);
    cvt4<<<dim3(256, 4), 256>>>((const float4*)Wq, (uint2*)hWq,
                                (const float4*)Wk, (uint2*)hWk,
                                (const float4*)Wv, (uint2*)hWv,
                                (const float4*)Wo, (uint2*)hWo);

    dim3 gg(DM / BN, NTOK / BM);   // (4, 128)
    gemm_h<__half><<<gg, NTHR, GEMM_SMEM>>>(hq,  hWq, bq, qh);
    gemm_h<__half><<<gg, NTHR, GEMM_SMEM>>>(hk,  hWk, bk, kh);
    gemm_h<__half><<<gg, NTHR, GEMM_SMEM>>>(hv,  hWv, bv, vh);
    head_attn<<<NTOK, 256>>>(qh, kh, vh, att);
    gemm_h<float><<<gg, NTHR, GEMM_SMEM>>>(att, hWo, bo, out);
}